// round 17
// baseline (speedup 1.0000x reference)
#include <cuda_runtime.h>
#include <cuda_fp16.h>
#include <math.h>
#include <stdint.h>

#define NSTEPS 50
#define BATCH  131072
#define TPB    128
#define NBLK   (BATCH / TPB)   // 1024

static __device__ float g_part[NBLK];
static __device__ int   g_cnt = 0;

typedef unsigned int u32;

__device__ __forceinline__ u32 smem_u32(const void* p) {
    u32 a;
    asm("{ .reg .u64 t; cvta.to.shared.u64 t, %1; cvt.u32.u64 %0, t; }" : "=r"(a) : "l"(p));
    return a;
}
__device__ __forceinline__ u32 cvt_f16x2(float lo, float hi) {
    u32 r; asm("cvt.rn.f16x2.f32 %0, %1, %2;" : "=r"(r) : "f"(hi), "f"(lo)); return r;
}
// cvt two fp32 -> f16x2, then relu on the packed pair (one max.f16x2)
__device__ __forceinline__ u32 relu_cvt(float a, float b) {
    u32 r = cvt_f16x2(a, b);
    u32 d;
    asm("max.f16x2 %0, %1, %2;" : "=r"(d) : "r"(r), "r"(0u));
    return d;
}
__device__ __forceinline__ float tanh_ap(float x) {
    float y; asm("tanh.approx.f32 %0, %1;" : "=f"(y) : "f"(x)); return y;
}
__device__ __forceinline__ void mma16816(float c[4], const u32 a[4], const u32 b[2]) {
    asm volatile("mma.sync.aligned.m16n8k16.row.col.f32.f16.f16.f32 "
                 "{%0,%1,%2,%3}, {%4,%5,%6,%7}, {%8,%9}, {%0,%1,%2,%3};"
                 : "+f"(c[0]), "+f"(c[1]), "+f"(c[2]), "+f"(c[3])
                 : "r"(a[0]), "r"(a[1]), "r"(a[2]), "r"(a[3]), "r"(b[0]), "r"(b[1]));
}
__device__ __forceinline__ void mma1688(float c[4], const u32 a[2], u32 b) {
    asm volatile("mma.sync.aligned.m16n8k8.row.col.f32.f16.f16.f32 "
                 "{%0,%1,%2,%3}, {%4,%5}, {%6}, {%0,%1,%2,%3};"
                 : "+f"(c[0]), "+f"(c[1]), "+f"(c[2]), "+f"(c[3])
                 : "r"(a[0]), "r"(a[1]), "r"(b));
}
__device__ __forceinline__ void ldsm2(u32 r[2], u32 addr) {
    asm volatile("ldmatrix.sync.aligned.m8n8.x2.shared.b16 {%0,%1}, [%2];"
                 : "=r"(r[0]), "=r"(r[1]) : "r"(addr));
}

__global__ void __launch_bounds__(TPB, 3)
bsde_kernel(const float* __restrict__ y0v, const float* __restrict__ Y0v,
            const float* __restrict__ qW1, const float* __restrict__ qb1,
            const float* __restrict__ qW2, const float* __restrict__ qb2,
            const float* __restrict__ qW3, const float* __restrict__ qb3,
            const float* __restrict__ zW1, const float* __restrict__ zb1,
            const float* __restrict__ zW2, const float* __restrict__ zb2,
            const float* __restrict__ zW3, const float* __restrict__ zb3,
            const float* __restrict__ dW, float* __restrict__ out) {
    __shared__ __align__(16) char sX[128 * 16];   // [row][8 f16]: 0-3 x_hi, 4-7 x_lo
    __shared__ __align__(16) float sP[128 * 4];   // [row]{z0,z1,z2,q}
    __shared__ float s_red[4];
    __shared__ int s_last;

    const int tid  = threadIdx.x;
    const int lane = tid & 31;
    const int wid  = tid >> 5;
    const int g    = lane >> 2;
    const int tg   = lane & 3;
    const int trunk = wid >> 1;   // 0 = z, 1 = q
    const int nsub  = wid & 1;    // m-half: m-tiles nsub*4 .. nsub*4+3

    const float* W1 = trunk ? qW1 : zW1;
    const float* B1 = trunk ? qb1 : zb1;
    const float* W2 = trunk ? qW2 : zW2;
    const float* B2 = trunk ? qb2 : zb2;

    // ---- B1 fragments (k8): k 0-3 = W1 rows (x_hi), k 4-7 = W1 rows again (x_lo) ----
    u32 B1f[8];
    #pragma unroll
    for (int nt = 0; nt < 8; nt++) {
        int n = nt * 8 + g;
        int k0 = tg * 2, k1 = tg * 2 + 1;
        B1f[nt] = cvt_f16x2(W1[(k0 & 3) * 64 + n], W1[(k1 & 3) * 64 + n]);
    }
    // ---- b1 accumulator-init values ----
    float b1c[16];
    #pragma unroll
    for (int nt = 0; nt < 8; nt++) {
        b1c[nt * 2]     = B1[nt * 8 + tg * 2];
        b1c[nt * 2 + 1] = B1[nt * 8 + tg * 2 + 1];
    }

    // ---- B2 fragments: full N=64 for this trunk ----
    u32 B2f[64];
    #pragma unroll
    for (int nt = 0; nt < 8; nt++) {
        int n = nt * 8 + g;
        #pragma unroll
        for (int kt = 0; kt < 4; kt++) {
            #pragma unroll
            for (int r = 0; r < 2; r++) {
                int k0 = kt * 16 + tg * 2 + r * 8;
                B2f[nt * 8 + kt * 2 + r] = cvt_f16x2(W2[k0 * 64 + n], W2[(k0 + 1) * 64 + n]);
            }
        }
    }
    // ---- b2 accumulator-init values ----
    float b2c[16];
    #pragma unroll
    for (int nt = 0; nt < 8; nt++) {
        b2c[nt * 2]     = B2[nt * 8 + tg * 2];
        b2c[nt * 2 + 1] = B2[nt * 8 + tg * 2 + 1];
    }

    // ---- B3 fragments: K=64, n = 3 (z) or 1 (q), zero-padded to 8 ----
    u32 B3f[8];
    #pragma unroll
    for (int kt = 0; kt < 4; kt++) {
        #pragma unroll
        for (int r = 0; r < 2; r++) {
            int kb = kt * 16 + tg * 2 + r * 8;
            float w0 = 0.f, w1 = 0.f;
            if (trunk == 0) {
                if (g < 3) { w0 = zW3[kb * 3 + g]; w1 = zW3[(kb + 1) * 3 + g]; }
            } else {
                if (g == 0) { w0 = qW3[kb]; w1 = qW3[kb + 1]; }
            }
            B3f[kt * 2 + r] = cvt_f16x2(w0, w1);
        }
    }

    // ---- ldmatrix lane address for X (16B rows, no swizzle needed) ----
    const u32 xb = smem_u32(sX);
    const u32 xoff = xb + (u32)((lane & 15) * 16);

    const float zb3_0 = zb3[0], zb3_1 = zb3[1], zb3_2 = zb3[2], qb3_0 = qb3[0];
    const int gp = blockIdx.x * TPB + tid;
    const float dt = 0.02f;
    const float sqdt = sqrtf(dt);
    float y0 = y0v[0], y1 = y0v[1], y2 = y0v[2];
    float Y  = Y0v[0];
    __syncthreads();

    for (int n = 0; n < NSTEPS; n++) {
        const float* dwp = dW + ((size_t)n * BATCH + gp) * 3;
        float dw0 = dwp[0] * sqdt;
        float dw1 = dwp[1] * sqdt;
        float dw2 = dwp[2] * sqdt;
        float t = (float)n * dt;

        // ---- store x hi/lo (exact fp32 via residual split): one 16B row ----
        {
            u32 h01 = cvt_f16x2(t,  y0);
            u32 h23 = cvt_f16x2(y1, y2);
            float2 f01 = __half22float2(*reinterpret_cast<__half2*>(&h01));
            float2 f23 = __half22float2(*reinterpret_cast<__half2*>(&h23));
            u32 l01 = cvt_f16x2(t  - f01.x, y0 - f01.y);
            u32 l23 = cvt_f16x2(y1 - f23.x, y2 - f23.y);
            *(uint4*)(sX + tid * 16) = make_uint4(h01, h23, l01, l23);
        }
        __syncthreads();   // X ready (also orders prev-step sP reads before new writes)

        // ---- preload all 4 m-tiles' X a-frags (removes ldsm from dependency chains) ----
        u32 axm[4][2];
        #pragma unroll
        for (int mt = 0; mt < 4; mt++)
            ldsm2(axm[mt], xoff + (u32)(((nsub * 4 + mt) * 16) * 16));

        // ---- this warp: 4 m-tiles, full 3-layer pipeline on tensor pipe ----
        #pragma unroll 1
        for (int mt = 0; mt < 4; mt++) {
            const int mrow = (nsub * 4 + mt) * 16;

            // layer 1 (k8, bias in accumulator)
            float c1[8][4];
            #pragma unroll
            for (int nt = 0; nt < 8; nt++) {
                c1[nt][0] = b1c[2*nt]; c1[nt][1] = b1c[2*nt+1];
                c1[nt][2] = b1c[2*nt]; c1[nt][3] = b1c[2*nt+1];
                mma1688(c1[nt], axm[mt], B1f[nt]);
            }
            // cvt + packed relu -> layer-2 A fragments
            u32 a2[16];
            #pragma unroll
            for (int kt = 0; kt < 4; kt++) {
                a2[kt * 4 + 0] = relu_cvt(c1[2*kt][0],   c1[2*kt][1]);
                a2[kt * 4 + 1] = relu_cvt(c1[2*kt][2],   c1[2*kt][3]);
                a2[kt * 4 + 2] = relu_cvt(c1[2*kt+1][0], c1[2*kt+1][1]);
                a2[kt * 4 + 3] = relu_cvt(c1[2*kt+1][2], c1[2*kt+1][3]);
            }
            // layer 2 (accumulators init with b2)
            float c2[8][4];
            #pragma unroll
            for (int nt = 0; nt < 8; nt++) {
                c2[nt][0] = b2c[2*nt]; c2[nt][1] = b2c[2*nt+1];
                c2[nt][2] = b2c[2*nt]; c2[nt][3] = b2c[2*nt+1];
            }
            #pragma unroll
            for (int kt = 0; kt < 4; kt++) {
                #pragma unroll
                for (int nt = 0; nt < 8; nt++)
                    mma16816(c2[nt], &a2[kt * 4], &B2f[nt * 8 + kt * 2]);
            }
            // cvt + packed relu -> layer-3 A fragments
            u32 a3[16];
            #pragma unroll
            for (int kt = 0; kt < 4; kt++) {
                a3[kt * 4 + 0] = relu_cvt(c2[2*kt][0],   c2[2*kt][1]);
                a3[kt * 4 + 1] = relu_cvt(c2[2*kt][2],   c2[2*kt][3]);
                a3[kt * 4 + 2] = relu_cvt(c2[2*kt+1][0], c2[2*kt+1][1]);
                a3[kt * 4 + 3] = relu_cvt(c2[2*kt+1][2], c2[2*kt+1][3]);
            }
            // layer 3: full K=64 in-warp -> direct z/q
            float c3[4] = {0.f, 0.f, 0.f, 0.f};
            #pragma unroll
            for (int kt = 0; kt < 4; kt++)
                mma16816(c3, &a3[kt * 4], &B3f[kt * 2]);

            // scatter: rows mrow+g, mrow+g+8 ; c3 cols = {tg*2, tg*2+1}
            int row = mrow + g;
            if (trunk == 0) {
                if (tg == 0) {        // cols 0,1 -> z0,z1
                    *(float2*)&sP[row * 4]       = make_float2(c3[0], c3[1]);
                    *(float2*)&sP[(row + 8) * 4] = make_float2(c3[2], c3[3]);
                } else if (tg == 1) { // col 2 -> z2
                    sP[row * 4 + 2]       = c3[0];
                    sP[(row + 8) * 4 + 2] = c3[2];
                }
            } else {
                if (tg == 0) {        // col 0 -> q
                    sP[row * 4 + 3]       = c3[0];
                    sP[(row + 8) * 4 + 3] = c3[2];
                }
            }
        }
        __syncthreads();   // P ready

        // ---- gather, SDE update ----
        float4 pv = *(const float4*)&sP[tid * 4];
        float z0 = zb3_0 + pv.x;
        float z1 = zb3_1 + pv.y;
        float z2 = zb3_2 + pv.z;
        float q  = qb3_0 + pv.w;

        float f  = 0.5f * q * q;
        float s0 = 0.2f + 0.1f * tanh_ap(y0);
        float s1 = 0.2f + 0.1f * tanh_ap(y1);
        float s2 = 0.2f + 0.1f * tanh_ap(y2);
        y0 += (q - y0) * dt + s0 * dw0;
        y1 += (q - y1) * dt + s1 * dw1;
        y2 += (q - y2) * dt + s2 * dw2;
        Y  += -f * dt + z0 * dw0 + z1 * dw1 + z2 * dw2;
        // next iteration's X barrier orders sP reads before next scatter
    }

    // ---- per-path loss + deterministic reduction ----
    float term = y0 * y0 + y1 * y1 + y2 * y2;
    float v = Y - term;
    v = v * v;
    #pragma unroll
    for (int off = 16; off > 0; off >>= 1)
        v += __shfl_down_sync(0xffffffffu, v, off);
    if ((tid & 31) == 0) s_red[wid] = v;
    __syncthreads();
    if (tid == 0) {
        g_part[blockIdx.x] = s_red[0] + s_red[1] + s_red[2] + s_red[3];
        __threadfence();
        int c = atomicAdd(&g_cnt, 1);
        s_last = (c == NBLK - 1);
    }
    __syncthreads();
    if (s_last) {
        __threadfence();
        float acc = 0.0f;
        for (int i = tid; i < NBLK; i += TPB) acc += g_part[i];
        #pragma unroll
        for (int off = 16; off > 0; off >>= 1)
            acc += __shfl_down_sync(0xffffffffu, acc, off);
        if ((tid & 31) == 0) s_red[wid] = acc;
        __syncthreads();
        if (tid == 0) {
            out[0] = (s_red[0] + s_red[1] + s_red[2] + s_red[3]) * (1.0f / (float)BATCH);
            g_cnt = 0;   // reset for next replay
        }
    }
}

extern "C" void kernel_launch(void* const* d_in, const int* in_sizes, int n_in,
                              void* d_out, int out_size) {
    const float* y0  = (const float*)d_in[0];
    const float* Y0  = (const float*)d_in[1];
    const float* qW1 = (const float*)d_in[2];
    const float* qb1 = (const float*)d_in[3];
    const float* qW2 = (const float*)d_in[4];
    const float* qb2 = (const float*)d_in[5];
    const float* qW3 = (const float*)d_in[6];
    const float* qb3 = (const float*)d_in[7];
    const float* zW1 = (const float*)d_in[8];
    const float* zb1 = (const float*)d_in[9];
    const float* zW2 = (const float*)d_in[10];
    const float* zb2 = (const float*)d_in[11];
    const float* zW3 = (const float*)d_in[12];
    const float* zb3 = (const float*)d_in[13];
    const float* dW  = (const float*)d_in[14];

    bsde_kernel<<<NBLK, TPB>>>(y0, Y0, qW1, qb1, qW2, qb2, qW3, qb3,
                               zW1, zb1, zW2, zb2, zW3, zb3, dW, (float*)d_out);
}